// round 10
// baseline (speedup 1.0000x reference)
#include <cuda_runtime.h>
#include <cstdint>

#define M_B 128
#define N_F 1024
#define K_F 1024
#define KSPLIT 8
#define BN 64
#define KCHUNK (K_F / KSPLIT)      /* 128 */
#define GRID 128                   /* 16 nb-groups x 8 ks — single wave, barrier-safe */

#define SA_STRIDE 132              /* conflict-free frag loads */
#define SB_STRIDE 72               /* conflict-free frag loads */
#define SMEM_BYTES ((128 * SA_STRIDE + KCHUNK * SB_STRIDE) * 4)   /* 104448 */

// Scratch (device globals: no allocation allowed in kernel_launch)
__device__ float g_partial[KSPLIT * M_B * N_F];   // 4 MB split-K partials
__device__ unsigned int g_cnt8[8 * 32];            // 8 barrier counters, 128B apart

// ---------------------------------------------------------------------------
__device__ __forceinline__ void cp_async16(void* smem, const void* gmem) {
    uint32_t s = (uint32_t)__cvta_generic_to_shared(smem);
    asm volatile("cp.async.cg.shared.global [%0], [%1], 16;\n" :: "r"(s), "l"(gmem));
}
__device__ __forceinline__ void cp_commit() {
    asm volatile("cp.async.commit_group;\n");
}
template <int N>
__device__ __forceinline__ void cp_wait() {
    asm volatile("cp.async.wait_group %0;\n" :: "n"(N));
}
__device__ __forceinline__ uint32_t f2tf32(float x) {
    uint32_t r;
    asm("cvt.rna.tf32.f32 %0, %1;" : "=r"(r) : "f"(x));
    return r;
}

// ---------------------------------------------------------------------------
// Persistent kernel, 128 CTAs (single wave), monolithic K-stage with an
// explicitly double-buffered fragment pipeline. Prep overlaps the cp.async
// fill; barrier uses 8 spread counters to avoid atomic serialization.
// ---------------------------------------------------------------------------
__global__ __launch_bounds__(256, 1) void fused_kernel(
        const float* __restrict__ input,
        const float* __restrict__ codes,
        const float* __restrict__ weight,
        const float* __restrict__ A,
        const float* __restrict__ Bm,
        const float* __restrict__ bias,
        const float* __restrict__ bctx,
        float* __restrict__ out) {
    extern __shared__ float smem[];
    float (*sA)[SA_STRIDE] = reinterpret_cast<float(*)[SA_STRIDE]>(smem);
    float (*sB)[SB_STRIDE] = reinterpret_cast<float(*)[SB_STRIDE]>(smem + 128 * SA_STRIDE);
    __shared__ float s_red[8][2];
    __shared__ unsigned int s_target;

    int tid = threadIdx.x;
    int bid = blockIdx.x;

    int nb = (bid & 15) * BN;          // 16 nb-groups
    int ks = bid >> 4;                 // 8 ks
    int k_base = ks * KCHUNK;

    int wid = tid >> 5, lane = tid & 31;
    int wm = wid & 3, wn = wid >> 2;
    int m_base = wm * 32, n_base = wn * 32;
    int g = lane >> 2, q = lane & 3;

    // ---- issue ALL loads for the whole K-chunk (max MLP) ----
    {
        int a_row = tid >> 5, a_c4 = (tid & 31) * 4;
        #pragma unroll
        for (int t = 0; t < 16; t++) {
            int row = a_row + t * 8;
            cp_async16(&sA[row][a_c4], input + row * K_F + k_base + a_c4);
        }
        int b_row = tid >> 4, b_c4 = (tid & 15) * 4;
        #pragma unroll
        for (int t = 0; t < 8; t++) {
            int row = b_row + t * 16;
            cp_async16(&sB[row][b_c4], weight + (k_base + row) * N_F + nb + b_c4);
        }
        cp_commit();
    }

    // ---- prep (overlaps the cp.async fill): CTA b = bid ----
    float v0, v1, d0, d1;
    {
        int b = bid;
        float4 x = *reinterpret_cast<const float4*>(input + b * K_F + tid * 4);
        const float2* A2 = reinterpret_cast<const float2*>(A);
        float2 a0 = A2[tid * 4 + 0];
        float2 a1 = A2[tid * 4 + 1];
        float2 a2 = A2[tid * 4 + 2];
        float2 a3 = A2[tid * 4 + 3];
        float p0 = x.x * a0.x + x.y * a1.x + x.z * a2.x + x.w * a3.x;
        float p1 = x.x * a0.y + x.y * a1.y + x.z * a2.y + x.w * a3.y;
        #pragma unroll
        for (int off = 16; off > 0; off >>= 1) {
            p0 += __shfl_xor_sync(0xFFFFFFFFu, p0, off);
            p1 += __shfl_xor_sync(0xFFFFFFFFu, p1, off);
        }
        if (lane == 0) { s_red[wid][0] = p0; s_red[wid][1] = p1; }
        __syncthreads();
        float u0 = 0.f, u1 = 0.f;
        #pragma unroll
        for (int i = 0; i < 8; i++) { u0 += s_red[i][0]; u1 += s_red[i][1]; }
        float c00 = codes[b * 4 + 0], c01 = codes[b * 4 + 1];
        float c10 = codes[b * 4 + 2], c11 = codes[b * 4 + 3];
        v0 = u0 * c00 + u1 * c10;
        v1 = u0 * c01 + u1 * c11;
        d0 = c00;
        d1 = c11;
    }

    float acc[2][4][4];
    #pragma unroll
    for (int mi = 0; mi < 2; mi++)
        #pragma unroll
        for (int ni = 0; ni < 4; ni++)
            #pragma unroll
            for (int r = 0; r < 4; r++) acc[mi][ni][r] = 0.f;

    cp_wait<0>();
    __syncthreads();

    // ---- explicitly double-buffered fragment pipeline, 16 kk steps ----
    uint32_t afr[2][2][4], bfr[2][4][2];

    auto load_frags = [&](int kk, int pb) {
        #pragma unroll
        for (int mi = 0; mi < 2; mi++) {
            int r0 = m_base + mi * 16 + g;
            afr[pb][mi][0] = f2tf32(sA[r0    ][kk + q    ]);
            afr[pb][mi][1] = f2tf32(sA[r0 + 8][kk + q    ]);
            afr[pb][mi][2] = f2tf32(sA[r0    ][kk + q + 4]);
            afr[pb][mi][3] = f2tf32(sA[r0 + 8][kk + q + 4]);
        }
        #pragma unroll
        for (int ni = 0; ni < 4; ni++) {
            int c0 = n_base + ni * 8 + g;
            bfr[pb][ni][0] = f2tf32(sB[kk + q    ][c0]);
            bfr[pb][ni][1] = f2tf32(sB[kk + q + 4][c0]);
        }
    };

    load_frags(0, 0);
    #pragma unroll
    for (int i = 0; i < 16; i++) {
        int pb = i & 1;
        if (i < 15) load_frags((i + 1) * 8, pb ^ 1);
        #pragma unroll
        for (int mi = 0; mi < 2; mi++)
            #pragma unroll
            for (int ni = 0; ni < 4; ni++) {
                asm volatile(
                    "mma.sync.aligned.m16n8k8.row.col.f32.tf32.tf32.f32 "
                    "{%0,%1,%2,%3}, {%4,%5,%6,%7}, {%8,%9}, {%0,%1,%2,%3};\n"
                    : "+f"(acc[mi][ni][0]), "+f"(acc[mi][ni][1]),
                      "+f"(acc[mi][ni][2]), "+f"(acc[mi][ni][3])
                    : "r"(afr[pb][mi][0]), "r"(afr[pb][mi][1]),
                      "r"(afr[pb][mi][2]), "r"(afr[pb][mi][3]),
                      "r"(bfr[pb][ni][0]), "r"(bfr[pb][ni][1]));
            }
    }

    // ---- write split-K partials ----
    {
        float* part = g_partial + ks * (M_B * N_F);
        #pragma unroll
        for (int mi = 0; mi < 2; mi++)
            #pragma unroll
            for (int ni = 0; ni < 4; ni++) {
                int row = m_base + mi * 16 + g;
                int col = nb + n_base + ni * 8 + q * 2;
                part[row * N_F + col]           = acc[mi][ni][0];
                part[row * N_F + col + 1]       = acc[mi][ni][1];
                part[(row + 8) * N_F + col]     = acc[mi][ni][2];
                part[(row + 8) * N_F + col + 1] = acc[mi][ni][3];
            }
    }

    // ========== grid barrier: 8 spread counters (16 arrivals each) ==========
    __threadfence();
    __syncthreads();
    if (tid == 0) {
        unsigned int ticket = atomicAdd(&g_cnt8[(bid & 7) * 32], 1u);
        s_target = (ticket / 16u + 1u) * 16u;   // end-of-replay count per counter
    }
    __syncthreads();
    if (tid < 8) {
        volatile unsigned int* c = &g_cnt8[tid * 32];
        unsigned int tgt = s_target;
        while (*c < tgt) { }
    }
    __syncthreads();
    __threadfence();

    // ============ Phase 2: split-K reduce + epilogue (CTA b = bid) ============
    {
        int b = bid;
        int j4 = tid * 4;
        float4 s = *reinterpret_cast<const float4*>(&g_partial[b * N_F + j4]);
        #pragma unroll
        for (int k = 1; k < KSPLIT; k++) {
            float4 p = *reinterpret_cast<const float4*>(
                &g_partial[k * (M_B * N_F) + b * N_F + j4]);
            s.x += p.x; s.y += p.y; s.z += p.z; s.w += p.w;
        }
        float4 bi = *reinterpret_cast<const float4*>(bias + j4);
        float4 B0 = *reinterpret_cast<const float4*>(Bm + j4);
        float4 B1 = *reinterpret_cast<const float4*>(Bm + N_F + j4);
        float4 e0 = *reinterpret_cast<const float4*>(bctx + j4);
        float4 e1 = *reinterpret_cast<const float4*>(bctx + N_F + j4);

        float4 o;
        o.x = s.x + bi.x + v0 * B0.x + v1 * B1.x + d0 * e0.x + d1 * e1.x;
        o.y = s.y + bi.y + v0 * B0.y + v1 * B1.y + d0 * e0.y + d1 * e1.y;
        o.z = s.z + bi.z + v0 * B0.z + v1 * B1.z + d0 * e0.z + d1 * e1.z;
        o.w = s.w + bi.w + v0 * B0.w + v1 * B1.w + d0 * e0.w + d1 * e1.w;
        *reinterpret_cast<float4*>(out + b * N_F + j4) = o;
    }
}

extern "C" void kernel_launch(void* const* d_in, const int* in_sizes, int n_in,
                              void* d_out, int out_size) {
    const float* input  = (const float*)d_in[0];
    const float* codes  = (const float*)d_in[1];
    const float* weight = (const float*)d_in[2];
    const float* A      = (const float*)d_in[3];
    const float* Bm     = (const float*)d_in[4];
    const float* bias   = (const float*)d_in[5];
    const float* bctx   = (const float*)d_in[6];
    float* out = (float*)d_out;

    cudaFuncSetAttribute(fused_kernel,
                         cudaFuncAttributeMaxDynamicSharedMemorySize, SMEM_BYTES);

    fused_kernel<<<GRID, 256, SMEM_BYTES>>>(input, codes, weight, A, Bm,
                                            bias, bctx, out);
}